// round 3
// baseline (speedup 1.0000x reference)
#include <cuda_runtime.h>
#include <cuda_bf16.h>
#include <cstdint>

// FrozenBNBEmbedding: fused blockwise-dequant + embedding gather.
// BLOCK (4096) == DIM (4096) => block id of any element of row r is r:
//   out[row, d] = code[ weight[token, d] ] * absmax[token]
//
// R2: bank-replicated code LUT (32 copies, one per smem bank) makes every
// LDS conflict-free: addr = (idx*32 + lane)*4 -> bank = lane. 4 rows per
// CTA amortize the 32KB LUT init.
//
// Inputs (metadata order):
//   d_in[0] = input  : int32 [4, 2048]      token ids (8192 rows)
//   d_in[1] = weight : int32 [50400, 4096]  int8 codes stored as int32
//   d_in[2] = absmax : fp32  [50400]        per-block scale (block == row)
//   d_in[3] = code   : fp32  [256]          dequant LUT
// Output: fp32 [4, 2048, 4096]

#define DIM 4096
#define VEC (DIM / 4)        // 1024 int4/float4 per row
#define ROWS_PER_CTA 4
#define NTHREADS 256

__global__ __launch_bounds__(NTHREADS, 7)
void bnb_embed_kernel(const int* __restrict__ tokens,
                      const int* __restrict__ weight,
                      const float* __restrict__ absmax,
                      const float* __restrict__ code,
                      float* __restrict__ out,
                      int n_rows)
{
    // 32 bank-replicated copies of the 256-entry LUT: 32 KB.
    __shared__ float s_lut[256 * 32];

    const int t = threadIdx.x;
    const int lane = t & 31;

    // Init: thread t writes entries j = t, t+256, ... ; bank(j) = j%32 varies
    // across consecutive threads -> conflict-free STS. code[j>>5] broadcasts.
    #pragma unroll
    for (int j = t; j < 256 * 32; j += NTHREADS)
        s_lut[j] = code[j >> 5];
    __syncthreads();

    const int row0 = blockIdx.x * ROWS_PER_CTA;

    #pragma unroll
    for (int r = 0; r < ROWS_PER_CTA; r++) {
        const int row = row0 + r;
        if (row >= n_rows) break;
        const int token = __ldg(&tokens[row]);
        const float amax = __ldg(&absmax[token]);

        const int4* __restrict__ src = reinterpret_cast<const int4*>(weight) +
                                       (size_t)token * VEC;
        float4* __restrict__ dst = reinterpret_cast<float4*>(out) +
                                   (size_t)row * VEC;

        #pragma unroll 4
        for (int i = t; i < VEC; i += NTHREADS) {
            int4 q = src[i];
            float4 v;
            v.x = s_lut[((q.x & 0xFF) << 5) | lane] * amax;
            v.y = s_lut[((q.y & 0xFF) << 5) | lane] * amax;
            v.z = s_lut[((q.z & 0xFF) << 5) | lane] * amax;
            v.w = s_lut[((q.w & 0xFF) << 5) | lane] * amax;
            dst[i] = v;
        }
    }
}

extern "C" void kernel_launch(void* const* d_in, const int* in_sizes, int n_in,
                              void* d_out, int out_size)
{
    const int*   tokens = (const int*)d_in[0];
    const int*   weight = (const int*)d_in[1];
    const float* absmax = (const float*)d_in[2];
    const float* code   = (const float*)d_in[3];
    float*       out    = (float*)d_out;

    int n_rows = in_sizes[0];  // 8192
    int grid = (n_rows + ROWS_PER_CTA - 1) / ROWS_PER_CTA;
    bnb_embed_kernel<<<grid, NTHREADS>>>(tokens, weight, absmax, code, out, n_rows);
}

// round 4
// speedup vs baseline: 1.1914x; 1.1914x over previous
#include <cuda_runtime.h>
#include <cuda_bf16.h>
#include <cstdint>

// FrozenBNBEmbedding: fused blockwise-dequant + embedding gather.
// BLOCK (4096) == DIM (4096) => block id of any element of row r is r:
//   out[row, d] = code[ weight[token, d] ] * absmax[token]
//
// R3: back to the R1 shape (occupancy/MLP is what binds, per the R2 regression),
// plus streaming stores (st.global.cs) so the 134MB write stream doesn't evict
// the gathered read set (~134MB, nearly L2-resident; ~8% duplicate tokens can
// hit L2 on re-read).
//
// Inputs (metadata order):
//   d_in[0] = input  : int32 [4, 2048]      token ids (8192 rows)
//   d_in[1] = weight : int32 [50400, 4096]  int8 codes stored as int32
//   d_in[2] = absmax : fp32  [50400]        per-block scale (block == row)
//   d_in[3] = code   : fp32  [256]          dequant LUT
// Output: fp32 [4, 2048, 4096]

#define DIM 4096
#define VEC (DIM / 4)  // 1024 int4/float4 per row
#define NTHREADS 256

__device__ __forceinline__ void stg_cs_v4(float4* p, float4 v) {
    asm volatile("st.global.cs.v4.f32 [%0], {%1, %2, %3, %4};"
                 :: "l"(p), "f"(v.x), "f"(v.y), "f"(v.z), "f"(v.w)
                 : "memory");
}

__global__ __launch_bounds__(NTHREADS, 8)
void bnb_embed_kernel(const int* __restrict__ tokens,
                      const int* __restrict__ weight,
                      const float* __restrict__ absmax,
                      const float* __restrict__ code,
                      float* __restrict__ out)
{
    __shared__ float s_code[256];
    const int t = threadIdx.x;
    if (t < 256) s_code[t] = code[t];
    __syncthreads();

    const int row = blockIdx.x;
    const int token = __ldg(&tokens[row]);
    const float amax = __ldg(&absmax[token]);

    const int4* __restrict__ src = reinterpret_cast<const int4*>(weight) +
                                   (size_t)token * VEC;
    float4* __restrict__ dst = reinterpret_cast<float4*>(out) +
                               (size_t)row * VEC;

    // VEC/NTHREADS = 4 iterations, fully unrolled -> 4 independent LDG.128
    // front-batched per thread for MLP.
    #pragma unroll
    for (int k = 0; k < VEC / NTHREADS; k++) {
        const int i = t + k * NTHREADS;
        int4 q = src[i];
        float4 v;
        v.x = s_code[q.x & 0xFF] * amax;
        v.y = s_code[q.y & 0xFF] * amax;
        v.z = s_code[q.z & 0xFF] * amax;
        v.w = s_code[q.w & 0xFF] * amax;
        stg_cs_v4(dst + i, v);
    }
}

extern "C" void kernel_launch(void* const* d_in, const int* in_sizes, int n_in,
                              void* d_out, int out_size)
{
    const int*   tokens = (const int*)d_in[0];
    const int*   weight = (const int*)d_in[1];
    const float* absmax = (const float*)d_in[2];
    const float* code   = (const float*)d_in[3];
    float*       out    = (float*)d_out;

    int n_rows = in_sizes[0];  // 8192
    bnb_embed_kernel<<<n_rows, NTHREADS>>>(tokens, weight, absmax, code, out);
}